// round 10
// baseline (speedup 1.0000x reference)
#include <cuda_runtime.h>
#include <cstdint>
#include <cstddef>

#define NS 512
#define NB 1024
#define NT 64

__device__ float g_partial[NB];
__device__ unsigned int g_ctr = 0;

typedef unsigned long long u64;

__device__ __forceinline__ u64 pack2(float lo, float hi) {
    u64 r; asm("mov.b64 %0, {%1, %2};" : "=l"(r) : "f"(lo), "f"(hi)); return r;
}
__device__ __forceinline__ void unpack2(u64 v, float& lo, float& hi) {
    asm("mov.b64 {%0, %1}, %2;" : "=f"(lo), "=f"(hi) : "l"(v));
}
__device__ __forceinline__ void fma2(u64& acc, u64 a, u64 b) {
    asm("fma.rn.f32x2 %0, %1, %2, %0;" : "+l"(acc) : "l"(a), "l"(b));
}
__device__ __forceinline__ u64 add2(u64 a, u64 b) {
    u64 r; asm("add.rn.f32x2 %0, %1, %2;" : "=l"(r) : "l"(a), "l"(b)); return r;
}
__device__ __forceinline__ u64 mul2(u64 a, u64 b) {
    u64 r; asm("mul.rn.f32x2 %0, %1, %2;" : "=l"(r) : "l"(a), "l"(b)); return r;
}
__device__ __forceinline__ float frcp(float x) {
    float r; asm("rcp.approx.f32 %0, %1;" : "=f"(r) : "f"(x)); return r;
}
__device__ __forceinline__ u64 shfl64(u64 v, int src) {
    unsigned lo = (unsigned)v, hi = (unsigned)(v >> 32);
    lo = __shfl_sync(0xffffffffu, lo, src);
    hi = __shfl_sync(0xffffffffu, hi, src);
    return ((u64)hi << 32) | lo;
}
__device__ __forceinline__ u64 shflx16_u64(u64 v) {
    unsigned lo = (unsigned)v, hi = (unsigned)(v >> 32);
    lo = __shfl_xor_sync(0xffffffffu, lo, 16);
    hi = __shfl_xor_sync(0xffffffffu, hi, 16);
    return ((u64)hi << 32) | lo;
}
__device__ __forceinline__ void cp_async16(void* smem_dst, const void* gsrc) {
    unsigned s = (unsigned)__cvta_generic_to_shared(smem_dst);
    asm volatile("cp.async.ca.shared.global [%0], [%1], 16;" :: "r"(s), "l"(gsrc));
}
#define CP_COMMIT() asm volatile("cp.async.commit_group;" ::: "memory")
#define CP_WAIT(n)  asm volatile("cp.async.wait_group %0;" :: "n"(n) : "memory")

__global__ void __launch_bounds__(32)
crf_kernel(const float* __restrict__ em,
           const float* __restrict__ trans,
           const float* __restrict__ start_t,
           const float* __restrict__ end_t,
           const int* __restrict__ tags,
           const int* __restrict__ mask,
           float* __restrict__ out) {
    // per-lane self-contained em ring: lane reads back exactly the 16B it copied
    __shared__ __align__(16) float emring[8][32][4];

    const int lane = threadIdx.x;        // one warp = one chain
    const int b    = blockIdx.x;
    const int c    = lane & 15;          // owns cols 4c..4c+3
    const int h    = lane >> 4;          // row half: row-pairs 16h..16h+15
    const size_t SSTR = (size_t)NB * NT;

    // ---------------- numerator: gold-path score ----------------
    float sc = 0.f;
    {
        int msum = 0;
#pragma unroll
        for (int k = 0; k < 16; k++) {
            int s = 1 + lane + (k << 5);
            if (s < NS) {
                int tp = tags[(s - 1) * NB + b];
                int tc = tags[s * NB + b];
                int mv = mask[s * NB + b];
                float term = trans[tp * NT + tc] + em[((size_t)s * NB + b) * NT + tc];
                sc += term * (float)mv;
                msum += mv;
            }
        }
#pragma unroll
        for (int off = 16; off; off >>= 1) {
            sc   += __shfl_xor_sync(0xffffffffu, sc, off);
            msum += __shfl_xor_sync(0xffffffffu, msum, off);
        }
        int t0 = tags[b];
        sc += start_t[t0] + em[(size_t)b * NT + t0];
        int seq_end = mask[b] + msum - 1;
        int lt = tags[(size_t)seq_end * NB + b];
        sc += end_t[lt];
    }

    // ---------------- mask bitset: lane l holds bits for steps 16l..16l+15 ----------
    unsigned mbits = 0;
#pragma unroll
    for (int k = 0; k < 16; k++) {
        int s = 16 * lane + k;
        mbits |= (unsigned)(mask[s * NB + b] & 1) << k;
    }

    // ---------------- start cp.async em pipeline: slots for steps 1..8 ----------------
    const float* em4src = em + (size_t)b * NT + 4 * c;   // my 16B per step
#pragma unroll
    for (int t = 1; t <= 8; t++) {
        cp_async16(&emring[t & 7][lane][0], em4src + (size_t)t * SSTR);
        CP_COMMIT();
    }

    // ---------------- E = exp(trans), row-pair packed: E<col>[k] = {E[r0][col], E[r0+1][col]} ----
    u64 E0[16], E1[16], E2[16], E3[16];
#pragma unroll
    for (int k = 0; k < 16; k++) {
        int r0 = 32 * h + 2 * k;
        float4 ta = *reinterpret_cast<const float4*>(trans + r0 * NT + 4 * c);
        float4 tb = *reinterpret_cast<const float4*>(trans + (r0 + 1) * NT + 4 * c);
        E0[k] = pack2(__expf(ta.x), __expf(tb.x));
        E1[k] = pack2(__expf(ta.y), __expf(tb.y));
        E2[k] = pack2(__expf(ta.z), __expf(tb.z));
        E3[k] = pack2(__expf(ta.w), __expf(tb.w));
    }

    // ---------------- init recursion state (replicated across halves) ----------------
    u64 y01, y23;
    {
        float4 e0 = *reinterpret_cast<const float4*>(em4src);
        float4 s4 = *reinterpret_cast<const float4*>(start_t + 4 * c);
        y01 = pack2(__expf(s4.x + e0.x), __expf(s4.y + e0.y));
        y23 = pack2(__expf(s4.z + e0.z), __expf(s4.w + e0.w));
    }
    float rcur = 1.f, lpend = 0.f, Mtot = 0.f;   // replicated in every lane

    u64 eem01, eem23;                            // exp(em[s]) for current step
    {
        CP_WAIT(7);                              // slot 1 resident (self-visible)
        float4 e1 = *reinterpret_cast<const float4*>(&emring[1][lane][0]);
        eem01 = pack2(__expf(e1.x), __expf(e1.y));
        eem23 = pack2(__expf(e1.z), __expf(e1.w));
    }

    // ---------------- sync-free branch-free forward recursion ----------------
    for (int s = 1; s < NS; s++) {
        CP_WAIT(6);                              // em[s+1] resident for end-of-iter read

        u64 a0 = 0, a1 = 0, a2 = 0, a3 = 0;
#pragma unroll
        for (int k = 0; k < 16; k += 2) {
            int src = 8 * h + (k >> 1);
            u64 qa = shfl64(y01, src);           // q row-pair 16h+k
            u64 qb = shfl64(y23, src);           // q row-pair 16h+k+1
            fma2(a0, qa, E0[k]);     fma2(a1, qa, E1[k]);
            fma2(a2, qa, E2[k]);     fma2(a3, qa, E3[k]);
            fma2(a0, qb, E0[k + 1]); fma2(a1, qb, E1[k + 1]);
            fma2(a2, qb, E2[k + 1]); fma2(a3, qb, E3[k + 1]);
        }
        a0 = add2(a0, shflx16_u64(a0));
        a1 = add2(a1, shflx16_u64(a1));
        a2 = add2(a2, shflx16_u64(a2));
        a3 = add2(a3, shflx16_u64(a3));
        float lo, hi, t0, t1, t2, t3;
        unpack2(a0, lo, hi); t0 = lo + hi;
        unpack2(a1, lo, hi); t1 = lo + hi;
        unpack2(a2, lo, hi); t2 = lo + hi;
        unpack2(a3, lo, hi); t3 = lo + hi;

        float a0raw = __shfl_sync(0xffffffffu, t0, 0);   // col-0 total
        int mk = (int)((__shfl_sync(0xffffffffu, mbits, s >> 4) >> (s & 15)) & 1u);

        u64 rp  = pack2(rcur, rcur);
        u64 c01 = mul2(mul2(pack2(t0, t1), rp), eem01);
        u64 c23 = mul2(mul2(pack2(t2, t3), rp), eem23);
        if (mk) { y01 = c01; y23 = c23; }

        float u0n = a0raw * rcur;
        if (mk) { Mtot += lpend; lpend = __logf(u0n); rcur = frcp(u0n); }

        // next eem from ring (em[s+1]); refill slot with em[s+8]
        float4 en = *reinterpret_cast<const float4*>(&emring[(s + 1) & 7][lane][0]);
        eem01 = pack2(__expf(en.x), __expf(en.y));
        eem23 = pack2(__expf(en.z), __expf(en.w));
        int t = (s + 8 < NS) ? (s + 8) : (NS - 1);
        cp_async16(&emring[(s + 8) & 7][lane][0], em4src + (size_t)t * SSTR);
        CP_COMMIT();
    }

    // ---------------- normalizer = Mtot + lag-pending + log(sum_j y_j e^{end_j}) ------
    {
        float4 e4 = *reinterpret_cast<const float4*>(end_t + 4 * c);
        float y0, y1, y2, y3;
        unpack2(y01, y0, y1); unpack2(y23, y2, y3);
        float v = y0 * __expf(e4.x) + y1 * __expf(e4.y)
                + y2 * __expf(e4.z) + y3 * __expf(e4.w);
#pragma unroll
        for (int off = 16; off; off >>= 1)
            v += __shfl_xor_sync(0xffffffffu, v, off);
        v *= 0.5f;   // halves contributed identical copies
        if (lane == 0) {
            g_partial[b] = sc - (Mtot + __logf(v));
            __threadfence();
        }
    }

    // ---------------- merged deterministic final reduction (last block) ----------------
    __syncwarp();
    int last = 0;
    if (lane == 0) {
        unsigned int old = atomicAdd(&g_ctr, 1);
        last = (old == (unsigned int)(gridDim.x - 1));
    }
    last = __shfl_sync(0xffffffffu, last, 0);
    if (last) {
        __threadfence();
        float s = 0.f;
#pragma unroll
        for (int i = 0; i < NB / 32; i++)
            s += g_partial[lane + i * 32];
#pragma unroll
        for (int off = 16; off; off >>= 1)
            s += __shfl_xor_sync(0xffffffffu, s, off);
        if (lane == 0) { out[0] = s; g_ctr = 0; }
    }
}

extern "C" void kernel_launch(void* const* d_in, const int* in_sizes, int n_in,
                              void* d_out, int out_size) {
    const float* em    = (const float*)d_in[0];
    const float* trans = (const float*)d_in[1];
    const float* st    = (const float*)d_in[2];
    const float* et    = (const float*)d_in[3];
    const int*   tags  = (const int*)d_in[4];
    const int*   mask  = (const int*)d_in[5];

    crf_kernel<<<NB, 32>>>(em, trans, st, et, tags, mask, (float*)d_out);
}

// round 11
// speedup vs baseline: 1.5669x; 1.5669x over previous
#include <cuda_runtime.h>
#include <cstdint>
#include <cstddef>

#define NS 512
#define NB 1024
#define NT 64
#define QSTRIDE 68   // 32 u64 (q0..31) + 2 pad + 32 u64 (q32..63) + 2 pad

__device__ float g_partial[NB];
__device__ unsigned int g_ctr = 0;

typedef unsigned long long u64;

__device__ __forceinline__ u64 pack2(float lo, float hi) {
    u64 r; asm("mov.b64 %0, {%1, %2};" : "=l"(r) : "f"(lo), "f"(hi)); return r;
}
__device__ __forceinline__ void unpack2(u64 v, float& lo, float& hi) {
    asm("mov.b64 {%0, %1}, %2;" : "=f"(lo), "=f"(hi) : "l"(v));
}
__device__ __forceinline__ void fma2(u64& acc, u64 a, u64 b) {
    asm("fma.rn.f32x2 %0, %1, %2, %0;" : "+l"(acc) : "l"(a), "l"(b));
}
__device__ __forceinline__ u64 add2(u64 a, u64 b) {
    u64 r; asm("add.rn.f32x2 %0, %1, %2;" : "=l"(r) : "l"(a), "l"(b)); return r;
}
__device__ __forceinline__ u64 mul2(u64 a, u64 b) {
    u64 r; asm("mul.rn.f32x2 %0, %1, %2;" : "=l"(r) : "l"(a), "l"(b)); return r;
}
__device__ __forceinline__ float frcp(float x) {
    float r; asm("rcp.approx.f32 %0, %1;" : "=f"(r) : "f"(x)); return r;
}
// exp(x) * 2^-6 as one FFMA + one MUFU.EX2
__device__ __forceinline__ float expm6(float x) {
    return exp2f(fmaf(x, 1.4426950408889634f, -6.0f));
}
__device__ __forceinline__ u64 shflx16_u64(u64 v) {
    unsigned lo = (unsigned)v, hi = (unsigned)(v >> 32);
    lo = __shfl_xor_sync(0xffffffffu, lo, 16);
    hi = __shfl_xor_sync(0xffffffffu, hi, 16);
    return ((u64)hi << 32) | lo;
}
__device__ __forceinline__ void sts128(u64* p, float a, float b, float c, float d) {
    asm volatile("st.shared.v4.f32 [%0], {%1, %2, %3, %4};"
                 :: "l"(p), "f"(a), "f"(b), "f"(c), "f"(d) : "memory");
}
__device__ __forceinline__ void cp_async8(void* smem_dst, const void* gsrc) {
    unsigned s = (unsigned)__cvta_generic_to_shared(smem_dst);
    asm volatile("cp.async.ca.shared.global [%0], [%1], 8;" :: "r"(s), "l"(gsrc));
}
#define CP_COMMIT() asm volatile("cp.async.commit_group;" ::: "memory")
#define CP_WAIT(n)  asm volatile("cp.async.wait_group %0;" :: "n"(n) : "memory")

__global__ void __launch_bounds__(32)
crf_kernel(const float* __restrict__ em,
           const float* __restrict__ trans,
           const float* __restrict__ start_t,
           const float* __restrict__ end_t,
           const int* __restrict__ tags,
           const int* __restrict__ mask,
           float* __restrict__ out) {
    __shared__ __align__(16) u64   qsm[2][QSTRIDE];
    __shared__ __align__(16) float emring[8][NT];

    const int lane = threadIdx.x;        // one warp = one chain
    const int b    = blockIdx.x;
    const int c    = lane & 15;          // owns cols 4c..4c+3
    const int h    = lane >> 4;          // row half
    const size_t SSTR = (size_t)NB * NT;

    // ---------------- numerator: gold-path score ----------------
    float sc = 0.f;
    int msum = 0;
    {
#pragma unroll
        for (int k = 0; k < 16; k++) {
            int s = 1 + lane + (k << 5);
            if (s < NS) {
                int tp = tags[(s - 1) * NB + b];
                int tc = tags[s * NB + b];
                int mv = mask[s * NB + b];
                float term = trans[tp * NT + tc] + em[((size_t)s * NB + b) * NT + tc];
                sc += term * (float)mv;
                msum += mv;
            }
        }
#pragma unroll
        for (int off = 16; off; off >>= 1) {
            sc   += __shfl_xor_sync(0xffffffffu, sc, off);
            msum += __shfl_xor_sync(0xffffffffu, msum, off);
        }
        int t0 = tags[b];
        sc += start_t[t0] + em[(size_t)b * NT + t0];
        int seq_end = mask[b] + msum - 1;
        int lt = tags[(size_t)seq_end * NB + b];
        sc += end_t[lt];
    }

    // ---------------- mask bitset: lane l holds bits for steps 16l..16l+15 ----------
    unsigned mbits = 0;
#pragma unroll
    for (int k = 0; k < 16; k++) {
        int s = 16 * lane + k;
        mbits |= (unsigned)(mask[s * NB + b] & 1) << k;
    }

    // ---------------- start cp.async em pipeline: slots for steps 1..8 ----------------
    const float* emb2l = em + (size_t)b * NT + 2 * lane;
#pragma unroll
    for (int t = 1; t <= 8; t++) {
        cp_async8(&emring[t & 7][2 * lane], emb2l + (size_t)t * SSTR);
        CP_COMMIT();
    }

    // ---------------- E = exp(trans): my 32 rows x my 4 cols ----------------
    u64 EA[32], EB[32];
#pragma unroll
    for (int i = 0; i < 32; i++) {
        float4 t4 = *reinterpret_cast<const float4*>(trans + (32 * h + i) * NT + 4 * c);
        EA[i] = pack2(__expf(t4.x), __expf(t4.y));
        EB[i] = pack2(__expf(t4.z), __expf(t4.w));
    }

    // ---------------- init recursion state (symmetric) ----------------
    const int sidx = 4 * c + ((c >= 8) ? 2 : 0);
    u64 y01, y23;
    {
        const float* emj4 = em + (size_t)b * NT + 4 * c;
        float4 e0 = *reinterpret_cast<const float4*>(emj4);
        float4 s4 = *reinterpret_cast<const float4*>(start_t + 4 * c);
        y01 = pack2(__expf(s4.x + e0.x), __expf(s4.y + e0.y));
        y23 = pack2(__expf(s4.z + e0.z), __expf(s4.w + e0.w));
        float y0, y1, y2, y3;
        unpack2(y01, y0, y1); unpack2(y23, y2, y3);
        if (h == 0) {
            sts128(qsm[1] + sidx,     y0, y0, y1, y1);
            sts128(qsm[1] + sidx + 2, y2, y2, y3, y3);
        }
    }
    float Mtot = 0.f;                            // renorm log accumulator (uniform)

    u64 eem01, eem23;                            // exp(em[s]) * 2^-6 for current step
    {
        CP_WAIT(7);
        __syncwarp();
        float4 e1 = *reinterpret_cast<const float4*>(&emring[1][4 * c]);
        eem01 = pack2(expm6(e1.x), expm6(e1.y));
        eem23 = pack2(expm6(e1.z), expm6(e1.w));
    }

// One forward step. P = parity (compile-time), RN = fused renormalization.
#define CRF_STEP(S, P, RN)                                                         \
    {                                                                              \
        CP_WAIT(6);                                                                \
        __syncwarp();                                                              \
        const u64* qh = qsm[P] + h * 34;                                           \
        u64 A0 = 0, A1 = 0, A2 = 0, A3 = 0;                                        \
        u64 B0 = 0, B1 = 0, B2 = 0, B3 = 0;                                        \
        _Pragma("unroll")                                                          \
        for (int i = 0; i < 32; i += 4) {                                          \
            ulonglong2 q0 = *reinterpret_cast<const ulonglong2*>(qh + i);          \
            ulonglong2 q1 = *reinterpret_cast<const ulonglong2*>(qh + i + 2);      \
            fma2(A0, q0.x, EA[i]);     fma2(B0, q0.x, EB[i]);                      \
            fma2(A1, q0.y, EA[i + 1]); fma2(B1, q0.y, EB[i + 1]);                  \
            fma2(A2, q1.x, EA[i + 2]); fma2(B2, q1.x, EB[i + 2]);                  \
            fma2(A3, q1.y, EA[i + 3]); fma2(B3, q1.y, EB[i + 3]);                  \
        }                                                                          \
        u64 S01 = add2(add2(A0, A1), add2(A2, A3));                                \
        u64 S23 = add2(add2(B0, B1), add2(B2, B3));                                \
        S01 = add2(S01, shflx16_u64(S01));                                         \
        S23 = add2(S23, shflx16_u64(S23));                                         \
        int mk = (int)((mword >> ((S) & 15)) & 1u);                                \
        u64 c01 = mul2(S01, eem01);                                                \
        u64 c23 = mul2(S23, eem23);                                                \
        if (mk) { y01 = c01; y23 = c23; }                                          \
        if (RN) {                                                                  \
            float f0, fxx; unpack2(y01, f0, fxx);                                  \
            float f = __shfl_sync(0xffffffffu, f0, 0);                             \
            float rf = frcp(f);                                                    \
            u64 rp = pack2(rf, rf);                                                \
            y01 = mul2(y01, rp); y23 = mul2(y23, rp);                              \
            Mtot += __logf(f);                                                     \
        }                                                                          \
        float y0, y1, y2, y3;                                                      \
        unpack2(y01, y0, y1); unpack2(y23, y2, y3);                                \
        u64* qn = qsm[(P) ^ 1];                                                    \
        if (h == 0) {                                                              \
            sts128(qn + sidx,     y0, y0, y1, y1);                                 \
            sts128(qn + sidx + 2, y2, y2, y3, y3);                                 \
        }                                                                          \
        float4 en = *reinterpret_cast<const float4*>(&emring[((S) + 1) & 7][4 * c]); \
        eem01 = pack2(expm6(en.x), expm6(en.y));                                   \
        eem23 = pack2(expm6(en.z), expm6(en.w));                                   \
        int t = ((S) + 8 < NS) ? ((S) + 8) : (NS - 1);                             \
        cp_async8(&emring[((S) + 8) & 7][2 * lane], emb2l + (size_t)t * SSTR);     \
        CP_COMMIT();                                                               \
    }

    // prologue: steps 1..7 (mask word from lane 0), renorm at step 7
    unsigned mword = __shfl_sync(0xffffffffu, mbits, 0);
    CRF_STEP(1, 1, false)
    CRF_STEP(2, 0, false)
    CRF_STEP(3, 1, false)
    CRF_STEP(4, 0, false)
    CRF_STEP(5, 1, false)
    CRF_STEP(6, 0, false)
    CRF_STEP(7, 1, true)

    // main: 63 blocks of 8 steps (s = 8o .. 8o+7), renorm fused into last step
    for (int o = 1; o < 64; o++) {
        const int s0 = o << 3;
        mword = __shfl_sync(0xffffffffu, mbits, o >> 1);
        CRF_STEP(s0,     0, false)
        CRF_STEP(s0 + 1, 1, false)
        CRF_STEP(s0 + 2, 0, false)
        CRF_STEP(s0 + 3, 1, false)
        CRF_STEP(s0 + 4, 0, false)
        CRF_STEP(s0 + 5, 1, false)
        CRF_STEP(s0 + 6, 0, false)
        CRF_STEP(s0 + 7, 1, true)
    }
#undef CRF_STEP

    // ---------------- normalizer = Mtot + msum*log(64) + log(sum_j y_j e^{end_j}) ------
    {
        float4 e4 = *reinterpret_cast<const float4*>(end_t + 4 * c);
        float y0, y1, y2, y3;
        unpack2(y01, y0, y1); unpack2(y23, y2, y3);
        float v = y0 * __expf(e4.x) + y1 * __expf(e4.y)
                + y2 * __expf(e4.z) + y3 * __expf(e4.w);
#pragma unroll
        for (int off = 16; off; off >>= 1)
            v += __shfl_xor_sync(0xffffffffu, v, off);
        v *= 0.5f;   // halves contributed identical copies
        if (lane == 0) {
            const float LOG64 = 4.1588830833596715f;
            g_partial[b] = sc - (Mtot + (float)msum * LOG64 + __logf(v));
            __threadfence();
        }
    }

    // ---------------- merged deterministic final reduction (last block) ----------------
    __syncwarp();
    int last = 0;
    if (lane == 0) {
        unsigned int old = atomicAdd(&g_ctr, 1);
        last = (old == (unsigned int)(gridDim.x - 1));
    }
    last = __shfl_sync(0xffffffffu, last, 0);
    if (last) {
        __threadfence();
        float s = 0.f;
#pragma unroll
        for (int i = 0; i < NB / 32; i++)
            s += g_partial[lane + i * 32];
#pragma unroll
        for (int off = 16; off; off >>= 1)
            s += __shfl_xor_sync(0xffffffffu, s, off);
        if (lane == 0) { out[0] = s; g_ctr = 0; }
    }
}

extern "C" void kernel_launch(void* const* d_in, const int* in_sizes, int n_in,
                              void* d_out, int out_size) {
    const float* em    = (const float*)d_in[0];
    const float* trans = (const float*)d_in[1];
    const float* st    = (const float*)d_in[2];
    const float* et    = (const float*)d_in[3];
    const int*   tags  = (const int*)d_in[4];
    const int*   mask  = (const int*)d_in[5];

    crf_kernel<<<NB, 32>>>(em, trans, st, et, tags, mask, (float*)d_out);
}

// round 12
// speedup vs baseline: 1.5861x; 1.0122x over previous
#include <cuda_runtime.h>
#include <cstdint>
#include <cstddef>

#define NS 512
#define NB 1024
#define NT 64

__device__ float g_partial[NB];
__device__ unsigned int g_ctr = 0;

typedef unsigned long long u64;

__device__ __forceinline__ u64 pack2(float lo, float hi) {
    u64 r; asm("mov.b64 %0, {%1, %2};" : "=l"(r) : "f"(lo), "f"(hi)); return r;
}
__device__ __forceinline__ void unpack2(u64 v, float& lo, float& hi) {
    asm("mov.b64 {%0, %1}, %2;" : "=f"(lo), "=f"(hi) : "l"(v));
}
__device__ __forceinline__ void fma2(u64& acc, u64 a, u64 b) {
    asm("fma.rn.f32x2 %0, %1, %2, %0;" : "+l"(acc) : "l"(a), "l"(b));
}
__device__ __forceinline__ u64 add2(u64 a, u64 b) {
    u64 r; asm("add.rn.f32x2 %0, %1, %2;" : "=l"(r) : "l"(a), "l"(b)); return r;
}
__device__ __forceinline__ u64 mul2(u64 a, u64 b) {
    u64 r; asm("mul.rn.f32x2 %0, %1, %2;" : "=l"(r) : "l"(a), "l"(b)); return r;
}
__device__ __forceinline__ float frcp(float x) {
    float r; asm("rcp.approx.f32 %0, %1;" : "=f"(r) : "f"(x)); return r;
}
// exp(x) * 2^-6 as one FFMA + one MUFU.EX2
__device__ __forceinline__ float expm6(float x) {
    return exp2f(fmaf(x, 1.4426950408889634f, -6.0f));
}
__device__ __forceinline__ u64 shflx16_u64(u64 v) {
    unsigned lo = (unsigned)v, hi = (unsigned)(v >> 32);
    lo = __shfl_xor_sync(0xffffffffu, lo, 16);
    hi = __shfl_xor_sync(0xffffffffu, hi, 16);
    return ((u64)hi << 32) | lo;
}
__device__ __forceinline__ void sts128f(float* p, float a, float b, float c, float d) {
    asm volatile("st.shared.v4.f32 [%0], {%1, %2, %3, %4};"
                 :: "l"(p), "f"(a), "f"(b), "f"(c), "f"(d) : "memory");
}
__device__ __forceinline__ void cp_async8(void* smem_dst, const void* gsrc) {
    unsigned s = (unsigned)__cvta_generic_to_shared(smem_dst);
    asm volatile("cp.async.ca.shared.global [%0], [%1], 8;" :: "r"(s), "l"(gsrc));
}
#define CP_COMMIT() asm volatile("cp.async.commit_group;" ::: "memory")
#define CP_WAIT(n)  asm volatile("cp.async.wait_group %0;" :: "n"(n) : "memory")

__global__ void __launch_bounds__(32)
crf_kernel(const float* __restrict__ em,
           const float* __restrict__ trans,
           const float* __restrict__ start_t,
           const float* __restrict__ end_t,
           const int* __restrict__ tags,
           const int* __restrict__ mask,
           float* __restrict__ out) {
    __shared__ __align__(16) float qsm[2][NT];      // plain y, col j at [j]
    __shared__ __align__(16) float emring[8][NT];

    const int lane = threadIdx.x;        // one warp = one chain
    const int b    = blockIdx.x;
    const int c    = lane & 15;          // owns cols 4c..4c+3
    const int h    = lane >> 4;          // accumulates source rows 32h..32h+31
    const size_t SSTR = (size_t)NB * NT;

    // ---------------- numerator: gold-path score ----------------
    float sc = 0.f;
    int msum = 0;
    {
#pragma unroll
        for (int k = 0; k < 16; k++) {
            int s = 1 + lane + (k << 5);
            if (s < NS) {
                int tp = tags[(s - 1) * NB + b];
                int tc = tags[s * NB + b];
                int mv = mask[s * NB + b];
                float term = trans[tp * NT + tc] + em[((size_t)s * NB + b) * NT + tc];
                sc += term * (float)mv;
                msum += mv;
            }
        }
#pragma unroll
        for (int off = 16; off; off >>= 1) {
            sc   += __shfl_xor_sync(0xffffffffu, sc, off);
            msum += __shfl_xor_sync(0xffffffffu, msum, off);
        }
        int t0 = tags[b];
        sc += start_t[t0] + em[(size_t)b * NT + t0];
        int seq_end = mask[b] + msum - 1;
        int lt = tags[(size_t)seq_end * NB + b];
        sc += end_t[lt];
    }

    // ---------------- mask bitset: lane l holds bits for steps 16l..16l+15 ----------
    unsigned mbits = 0;
#pragma unroll
    for (int k = 0; k < 16; k++) {
        int s = 16 * lane + k;
        mbits |= (unsigned)(mask[s * NB + b] & 1) << k;
    }

    // ---------------- start cp.async em pipeline: slots for steps 1..8 ----------------
    const float* emb2l = em + (size_t)b * NT + 2 * lane;
#pragma unroll
    for (int t = 1; t <= 8; t++) {
        cp_async8(&emring[t & 7][2 * lane], emb2l + (size_t)t * SSTR);
        CP_COMMIT();
    }

    // ---------------- E row-pair packed: E<j>[k] = {E[r0][col_j], E[r0+1][col_j]} ----
    // r0 = 32h + 2k, col_j = 4c + j
    u64 E0[16], E1[16], E2[16], E3[16];
#pragma unroll
    for (int k = 0; k < 16; k++) {
        int r0 = 32 * h + 2 * k;
        float4 ta = *reinterpret_cast<const float4*>(trans + r0 * NT + 4 * c);
        float4 tb = *reinterpret_cast<const float4*>(trans + (r0 + 1) * NT + 4 * c);
        E0[k] = pack2(__expf(ta.x), __expf(tb.x));
        E1[k] = pack2(__expf(ta.y), __expf(tb.y));
        E2[k] = pack2(__expf(ta.z), __expf(tb.z));
        E3[k] = pack2(__expf(ta.w), __expf(tb.w));
    }

    // ---------------- init recursion state (replicated across halves) ----------------
    u64 y01, y23;
    {
        const float* emj4 = em + (size_t)b * NT + 4 * c;
        float4 e0 = *reinterpret_cast<const float4*>(emj4);
        float4 s4 = *reinterpret_cast<const float4*>(start_t + 4 * c);
        y01 = pack2(__expf(s4.x + e0.x), __expf(s4.y + e0.y));
        y23 = pack2(__expf(s4.z + e0.z), __expf(s4.w + e0.w));
        float y0, y1, y2, y3;
        unpack2(y01, y0, y1); unpack2(y23, y2, y3);
        if (h == 0)
            sts128f(&qsm[1][4 * c], y0, y1, y2, y3);
    }
    float Mtot = 0.f;                            // renorm log accumulator (uniform)

    u64 eem01, eem23;                            // exp(em[s]) * 2^-6 for current step
    {
        CP_WAIT(7);
        __syncwarp();
        float4 e1 = *reinterpret_cast<const float4*>(&emring[1][4 * c]);
        eem01 = pack2(expm6(e1.x), expm6(e1.y));
        eem23 = pack2(expm6(e1.z), expm6(e1.w));
    }

// One forward step. P = parity (compile-time), RN = fused renormalization.
#define CRF_STEP(S, P, RN)                                                         \
    {                                                                              \
        CP_WAIT(6);                                                                \
        __syncwarp();                                                              \
        const ulonglong2* q2 = reinterpret_cast<const ulonglong2*>(&qsm[P][32 * h]); \
        u64 a0 = 0, a1 = 0, a2 = 0, a3 = 0;                                        \
        u64 b0 = 0, b1 = 0, b2 = 0, b3 = 0;                                        \
        _Pragma("unroll")                                                          \
        for (int m = 0; m < 8; m++) {                                              \
            ulonglong2 Q = q2[m];                                                  \
            fma2(a0, Q.x, E0[2 * m]);     fma2(a1, Q.x, E1[2 * m]);                \
            fma2(a2, Q.x, E2[2 * m]);     fma2(a3, Q.x, E3[2 * m]);                \
            fma2(b0, Q.y, E0[2 * m + 1]); fma2(b1, Q.y, E1[2 * m + 1]);            \
            fma2(b2, Q.y, E2[2 * m + 1]); fma2(b3, Q.y, E3[2 * m + 1]);            \
        }                                                                          \
        u64 A0 = add2(a0, b0), A1 = add2(a1, b1);                                  \
        u64 A2 = add2(a2, b2), A3 = add2(a3, b3);                                  \
        A0 = add2(A0, shflx16_u64(A0));                                            \
        A1 = add2(A1, shflx16_u64(A1));                                            \
        A2 = add2(A2, shflx16_u64(A2));                                            \
        A3 = add2(A3, shflx16_u64(A3));                                            \
        float lo, hi, t0, t1, t2, t3;                                              \
        unpack2(A0, lo, hi); t0 = lo + hi;                                         \
        unpack2(A1, lo, hi); t1 = lo + hi;                                         \
        unpack2(A2, lo, hi); t2 = lo + hi;                                         \
        unpack2(A3, lo, hi); t3 = lo + hi;                                         \
        int mk = (int)((mword >> ((S) & 15)) & 1u);                                \
        u64 c01 = mul2(pack2(t0, t1), eem01);                                      \
        u64 c23 = mul2(pack2(t2, t3), eem23);                                      \
        if (mk) { y01 = c01; y23 = c23; }                                          \
        if (RN) {                                                                  \
            float f0, fxx; unpack2(y01, f0, fxx);                                  \
            float f = __shfl_sync(0xffffffffu, f0, 0);                             \
            float rf = frcp(f);                                                    \
            u64 rp = pack2(rf, rf);                                                \
            y01 = mul2(y01, rp); y23 = mul2(y23, rp);                              \
            Mtot += __logf(f);                                                     \
        }                                                                          \
        float y0, y1, y2, y3;                                                      \
        unpack2(y01, y0, y1); unpack2(y23, y2, y3);                                \
        if (h == 0)                                                                \
            sts128f(&qsm[(P) ^ 1][4 * c], y0, y1, y2, y3);                         \
        float4 en = *reinterpret_cast<const float4*>(&emring[((S) + 1) & 7][4 * c]); \
        eem01 = pack2(expm6(en.x), expm6(en.y));                                   \
        eem23 = pack2(expm6(en.z), expm6(en.w));                                   \
        int t = ((S) + 8 < NS) ? ((S) + 8) : (NS - 1);                             \
        cp_async8(&emring[((S) + 8) & 7][2 * lane], emb2l + (size_t)t * SSTR);     \
        CP_COMMIT();                                                               \
    }

    // prologue: steps 1..7, renorm at step 7
    unsigned mword = __shfl_sync(0xffffffffu, mbits, 0);
    CRF_STEP(1, 1, false)
    CRF_STEP(2, 0, false)
    CRF_STEP(3, 1, false)
    CRF_STEP(4, 0, false)
    CRF_STEP(5, 1, false)
    CRF_STEP(6, 0, false)
    CRF_STEP(7, 1, true)

    // main: 63 blocks of 8 steps, renorm fused into last step of each block
    for (int o = 1; o < 64; o++) {
        const int s0 = o << 3;
        mword = __shfl_sync(0xffffffffu, mbits, o >> 1);
        CRF_STEP(s0,     0, false)
        CRF_STEP(s0 + 1, 1, false)
        CRF_STEP(s0 + 2, 0, false)
        CRF_STEP(s0 + 3, 1, false)
        CRF_STEP(s0 + 4, 0, false)
        CRF_STEP(s0 + 5, 1, false)
        CRF_STEP(s0 + 6, 0, false)
        CRF_STEP(s0 + 7, 1, true)
    }
#undef CRF_STEP

    // ---------------- normalizer = Mtot + msum*log(64) + log(sum_j y_j e^{end_j}) ------
    {
        float4 e4 = *reinterpret_cast<const float4*>(end_t + 4 * c);
        float y0, y1, y2, y3;
        unpack2(y01, y0, y1); unpack2(y23, y2, y3);
        float v = y0 * __expf(e4.x) + y1 * __expf(e4.y)
                + y2 * __expf(e4.z) + y3 * __expf(e4.w);
#pragma unroll
        for (int off = 16; off; off >>= 1)
            v += __shfl_xor_sync(0xffffffffu, v, off);
        v *= 0.5f;   // halves contributed identical copies
        if (lane == 0) {
            const float LOG64 = 4.1588830833596715f;
            g_partial[b] = sc - (Mtot + (float)msum * LOG64 + __logf(v));
            __threadfence();
        }
    }

    // ---------------- merged deterministic final reduction (last block) ----------------
    __syncwarp();
    int last = 0;
    if (lane == 0) {
        unsigned int old = atomicAdd(&g_ctr, 1);
        last = (old == (unsigned int)(gridDim.x - 1));
    }
    last = __shfl_sync(0xffffffffu, last, 0);
    if (last) {
        __threadfence();
        float s = 0.f;
#pragma unroll
        for (int i = 0; i < NB / 32; i++)
            s += g_partial[lane + i * 32];
#pragma unroll
        for (int off = 16; off; off >>= 1)
            s += __shfl_xor_sync(0xffffffffu, s, off);
        if (lane == 0) { out[0] = s; g_ctr = 0; }
    }
}

extern "C" void kernel_launch(void* const* d_in, const int* in_sizes, int n_in,
                              void* d_out, int out_size) {
    const float* em    = (const float*)d_in[0];
    const float* trans = (const float*)d_in[1];
    const float* st    = (const float*)d_in[2];
    const float* et    = (const float*)d_in[3];
    const int*   tags  = (const int*)d_in[4];
    const int*   mask  = (const int*)d_in[5];

    crf_kernel<<<NB, 32>>>(em, trans, st, et, tags, mask, (float*)d_out);
}

// round 13
// speedup vs baseline: 1.6034x; 1.0109x over previous
#include <cuda_runtime.h>
#include <cstdint>
#include <cstddef>

#define NS 512
#define NB 1024
#define NT 64

__device__ float g_partial[NB];
__device__ unsigned int g_ctr = 0;

typedef unsigned long long u64;

__device__ __forceinline__ u64 pack2(float lo, float hi) {
    u64 r; asm("mov.b64 %0, {%1, %2};" : "=l"(r) : "f"(lo), "f"(hi)); return r;
}
__device__ __forceinline__ void unpack2(u64 v, float& lo, float& hi) {
    asm("mov.b64 {%0, %1}, %2;" : "=f"(lo), "=f"(hi) : "l"(v));
}
__device__ __forceinline__ void fma2(u64& acc, u64 a, u64 b) {
    asm("fma.rn.f32x2 %0, %1, %2, %0;" : "+l"(acc) : "l"(a), "l"(b));
}
__device__ __forceinline__ u64 add2(u64 a, u64 b) {
    u64 r; asm("add.rn.f32x2 %0, %1, %2;" : "=l"(r) : "l"(a), "l"(b)); return r;
}
__device__ __forceinline__ u64 mul2(u64 a, u64 b) {
    u64 r; asm("mul.rn.f32x2 %0, %1, %2;" : "=l"(r) : "l"(a), "l"(b)); return r;
}
__device__ __forceinline__ float frcp(float x) {
    float r; asm("rcp.approx.f32 %0, %1;" : "=f"(r) : "f"(x)); return r;
}
// exp(x) * 2^-6 as one FFMA + one MUFU.EX2
__device__ __forceinline__ float expm6(float x) {
    return exp2f(fmaf(x, 1.4426950408889634f, -6.0f));
}
__device__ __forceinline__ void sts128f(float* p, float a, float b, float c, float d) {
    asm volatile("st.shared.v4.f32 [%0], {%1, %2, %3, %4};"
                 :: "l"(p), "f"(a), "f"(b), "f"(c), "f"(d) : "memory");
}
__device__ __forceinline__ void cp_async8(void* smem_dst, const void* gsrc) {
    unsigned s = (unsigned)__cvta_generic_to_shared(smem_dst);
    asm volatile("cp.async.ca.shared.global [%0], [%1], 8;" :: "r"(s), "l"(gsrc));
}
#define CP_COMMIT() asm volatile("cp.async.commit_group;" ::: "memory")
#define CP_WAIT(n)  asm volatile("cp.async.wait_group %0;" :: "n"(n) : "memory")

__global__ void __launch_bounds__(32)
crf_kernel(const float* __restrict__ em,
           const float* __restrict__ trans,
           const float* __restrict__ start_t,
           const float* __restrict__ end_t,
           const int* __restrict__ tags,
           const int* __restrict__ mask,
           float* __restrict__ out) {
    __shared__ __align__(16) u64   qsm[2][NT];     // duplicated pairs {y_j, y_j}
    __shared__ __align__(16) float emring[8][NT];

    const int lane = threadIdx.x;        // one warp = one chain
    const int b    = blockIdx.x;
    const int c0   = 2 * lane;           // my two columns: c0, c0+1
    const size_t SSTR = (size_t)NB * NT;

    // ---------------- numerator: gold-path score ----------------
    float sc = 0.f;
    int msum = 0;
    {
#pragma unroll
        for (int k = 0; k < 16; k++) {
            int s = 1 + lane + (k << 5);
            if (s < NS) {
                int tp = tags[(s - 1) * NB + b];
                int tc = tags[s * NB + b];
                int mv = mask[s * NB + b];
                float term = trans[tp * NT + tc] + em[((size_t)s * NB + b) * NT + tc];
                sc += term * (float)mv;
                msum += mv;
            }
        }
#pragma unroll
        for (int off = 16; off; off >>= 1) {
            sc   += __shfl_xor_sync(0xffffffffu, sc, off);
            msum += __shfl_xor_sync(0xffffffffu, msum, off);
        }
        int t0 = tags[b];
        sc += start_t[t0] + em[(size_t)b * NT + t0];
        int seq_end = mask[b] + msum - 1;
        int lt = tags[(size_t)seq_end * NB + b];
        sc += end_t[lt];
    }

    // ---------------- mask bitset: lane l holds bits for steps 16l..16l+15 ----------
    unsigned mbits = 0;
#pragma unroll
    for (int k = 0; k < 16; k++) {
        int s = 16 * lane + k;
        mbits |= (unsigned)(mask[s * NB + b] & 1) << k;
    }

    // ---------------- start cp.async em pipeline: slots for steps 1..8 ----------------
    // lane copies exactly its own 8B (cols c0, c0+1) -> self-visible after wait
    const float* emb2l = em + (size_t)b * NT + c0;
#pragma unroll
    for (int t = 1; t <= 8; t++) {
        cp_async8(&emring[t & 7][c0], emb2l + (size_t)t * SSTR);
        CP_COMMIT();
    }

    // ---------------- E = exp(trans): all 64 rows x my 2 cols (64 u64) ----------------
    u64 Ecol[NT];
#pragma unroll
    for (int i = 0; i < NT; i++) {
        float2 tr = *reinterpret_cast<const float2*>(trans + i * NT + c0);
        Ecol[i] = pack2(__expf(tr.x), __expf(tr.y));
    }

    // ---------------- init recursion state ----------------
    u64 y01;
    {
        float2 e0 = *reinterpret_cast<const float2*>(emb2l);
        float2 s2 = *reinterpret_cast<const float2*>(start_t + c0);
        y01 = pack2(__expf(s2.x + e0.x), __expf(s2.y + e0.y));
        float y0, y1; unpack2(y01, y0, y1);
        sts128f(reinterpret_cast<float*>(&qsm[1][c0]), y0, y0, y1, y1);
    }
    float Mtot = 0.f;                            // renorm log accumulator (uniform)

    u64 eem01;                                   // exp(em[s]) * 2^-6 for current step
    {
        CP_WAIT(7);
        float2 e1 = *reinterpret_cast<const float2*>(&emring[1][c0]);
        eem01 = pack2(expm6(e1.x), expm6(e1.y));
    }
    __syncwarp();

// One forward step. P = parity (compile-time), RN = fused renormalization.
#define CRF_STEP(S, P, RN)                                                         \
    {                                                                              \
        const ulonglong2* q2 = reinterpret_cast<const ulonglong2*>(qsm[P]);        \
        u64 a0 = 0, a1 = 0, a2 = 0, a3 = 0;                                        \
        u64 a4 = 0, a5 = 0, a6 = 0, a7 = 0;                                        \
        _Pragma("unroll")                                                          \
        for (int m = 0; m < 8; m++) {                                              \
            ulonglong2 qA = q2[4 * m];                                             \
            ulonglong2 qB = q2[4 * m + 1];                                         \
            ulonglong2 qC = q2[4 * m + 2];                                         \
            ulonglong2 qD = q2[4 * m + 3];                                         \
            fma2(a0, qA.x, Ecol[8 * m]);     fma2(a1, qA.y, Ecol[8 * m + 1]);      \
            fma2(a2, qB.x, Ecol[8 * m + 2]); fma2(a3, qB.y, Ecol[8 * m + 3]);      \
            fma2(a4, qC.x, Ecol[8 * m + 4]); fma2(a5, qC.y, Ecol[8 * m + 5]);      \
            fma2(a6, qD.x, Ecol[8 * m + 6]); fma2(a7, qD.y, Ecol[8 * m + 7]);      \
        }                                                                          \
        u64 acc = add2(add2(add2(a0, a1), add2(a2, a3)),                           \
                       add2(add2(a4, a5), add2(a6, a7)));                          \
        int mk = (int)((mword >> ((S) & 15)) & 1u);                                \
        u64 cnew = mul2(acc, eem01);                                               \
        if (mk) y01 = cnew;                                                        \
        if (RN) {                                                                  \
            float f0, fx; unpack2(y01, f0, fx);                                    \
            float f = __shfl_sync(0xffffffffu, f0, 0);                             \
            float rf = frcp(f);                                                    \
            y01 = mul2(y01, pack2(rf, rf));                                        \
            Mtot += __logf(f);                                                     \
        }                                                                          \
        float y0, y1; unpack2(y01, y0, y1);                                        \
        sts128f(reinterpret_cast<float*>(&qsm[(P) ^ 1][c0]), y0, y0, y1, y1);      \
        __syncwarp();                                                              \
        CP_WAIT(6);                                                                \
        float2 en = *reinterpret_cast<const float2*>(&emring[((S) + 1) & 7][c0]);  \
        eem01 = pack2(expm6(en.x), expm6(en.y));                                   \
        int t = ((S) + 8 < NS) ? ((S) + 8) : (NS - 1);                             \
        cp_async8(&emring[((S) + 8) & 7][c0], emb2l + (size_t)t * SSTR);           \
        CP_COMMIT();                                                               \
    }

    // prologue: steps 1..7, renorm at step 7
    unsigned mword = __shfl_sync(0xffffffffu, mbits, 0);
    CRF_STEP(1, 1, false)
    CRF_STEP(2, 0, false)
    CRF_STEP(3, 1, false)
    CRF_STEP(4, 0, false)
    CRF_STEP(5, 1, false)
    CRF_STEP(6, 0, false)
    CRF_STEP(7, 1, true)

    // main: 63 blocks of 8 steps, renorm fused into last step of each block
    for (int o = 1; o < 64; o++) {
        const int s0 = o << 3;
        mword = __shfl_sync(0xffffffffu, mbits, o >> 1);
        CRF_STEP(s0,     0, false)
        CRF_STEP(s0 + 1, 1, false)
        CRF_STEP(s0 + 2, 0, false)
        CRF_STEP(s0 + 3, 1, false)
        CRF_STEP(s0 + 4, 0, false)
        CRF_STEP(s0 + 5, 1, false)
        CRF_STEP(s0 + 6, 0, false)
        CRF_STEP(s0 + 7, 1, true)
    }
#undef CRF_STEP

    // ---------------- normalizer = Mtot + msum*log(64) + log(sum_j y_j e^{end_j}) ------
    {
        float2 e2 = *reinterpret_cast<const float2*>(end_t + c0);
        float y0, y1; unpack2(y01, y0, y1);
        float v = y0 * __expf(e2.x) + y1 * __expf(e2.y);
#pragma unroll
        for (int off = 16; off; off >>= 1)
            v += __shfl_xor_sync(0xffffffffu, v, off);
        if (lane == 0) {
            const float LOG64 = 4.1588830833596715f;
            g_partial[b] = sc - (Mtot + (float)msum * LOG64 + __logf(v));
            __threadfence();
        }
    }

    // ---------------- merged deterministic final reduction (last block) ----------------
    __syncwarp();
    int last = 0;
    if (lane == 0) {
        unsigned int old = atomicAdd(&g_ctr, 1);
        last = (old == (unsigned int)(gridDim.x - 1));
    }
    last = __shfl_sync(0xffffffffu, last, 0);
    if (last) {
        __threadfence();
        float s = 0.f;
#pragma unroll
        for (int i = 0; i < NB / 32; i++)
            s += g_partial[lane + i * 32];
#pragma unroll
        for (int off = 16; off; off >>= 1)
            s += __shfl_xor_sync(0xffffffffu, s, off);
        if (lane == 0) { out[0] = s; g_ctr = 0; }
    }
}

extern "C" void kernel_launch(void* const* d_in, const int* in_sizes, int n_in,
                              void* d_out, int out_size) {
    const float* em    = (const float*)d_in[0];
    const float* trans = (const float*)d_in[1];
    const float* st    = (const float*)d_in[2];
    const float* et    = (const float*)d_in[3];
    const int*   tags  = (const int*)d_in[4];
    const int*   mask  = (const int*)d_in[5];

    crf_kernel<<<NB, 32>>>(em, trans, st, et, tags, mask, (float*)d_out);
}

// round 14
// speedup vs baseline: 1.8317x; 1.1424x over previous
#include <cuda_runtime.h>
#include <cstdint>
#include <cstddef>

#define NS 512
#define NB 1024
#define NT 64

__device__ float g_partial[NB];
__device__ unsigned int g_ctr = 0;

typedef unsigned long long u64;

__device__ __forceinline__ u64 pack2(float lo, float hi) {
    u64 r; asm("mov.b64 %0, {%1, %2};" : "=l"(r) : "f"(lo), "f"(hi)); return r;
}
__device__ __forceinline__ void unpack2(u64 v, float& lo, float& hi) {
    asm("mov.b64 {%0, %1}, %2;" : "=f"(lo), "=f"(hi) : "l"(v));
}
__device__ __forceinline__ void fma2(u64& acc, u64 a, u64 b) {
    asm("fma.rn.f32x2 %0, %1, %2, %0;" : "+l"(acc) : "l"(a), "l"(b));
}
__device__ __forceinline__ u64 add2(u64 a, u64 b) {
    u64 r; asm("add.rn.f32x2 %0, %1, %2;" : "=l"(r) : "l"(a), "l"(b)); return r;
}
__device__ __forceinline__ u64 mul2(u64 a, u64 b) {
    u64 r; asm("mul.rn.f32x2 %0, %1, %2;" : "=l"(r) : "l"(a), "l"(b)); return r;
}
__device__ __forceinline__ float frcp(float x) {
    float r; asm("rcp.approx.f32 %0, %1;" : "=f"(r) : "f"(x)); return r;
}
// exp(x) * 2^-6 as one FFMA + one MUFU.EX2
__device__ __forceinline__ float expm6(float x) {
    return exp2f(fmaf(x, 1.4426950408889634f, -6.0f));
}
__device__ __forceinline__ void sts64(u64* p, u64 v) {
    asm volatile("st.shared.b64 [%0], %1;" :: "l"(p), "l"(v) : "memory");
}
__device__ __forceinline__ void cp_async8(void* smem_dst, const void* gsrc) {
    unsigned s = (unsigned)__cvta_generic_to_shared(smem_dst);
    asm volatile("cp.async.ca.shared.global [%0], [%1], 8;" :: "r"(s), "l"(gsrc));
}
#define CP_COMMIT() asm volatile("cp.async.commit_group;" ::: "memory")
#define CP_WAIT(n)  asm volatile("cp.async.wait_group %0;" :: "n"(n) : "memory")

__global__ void __launch_bounds__(32)
crf_kernel(const float* __restrict__ em,
           const float* __restrict__ trans,
           const float* __restrict__ start_t,
           const float* __restrict__ end_t,
           const int* __restrict__ tags,
           const int* __restrict__ mask,
           float* __restrict__ out) {
    __shared__ __align__(16) u64   qsm[2][32];     // slot l = {y_{2l}, y_{2l+1}}
    __shared__ __align__(16) float emring[8][NT];

    const int lane = threadIdx.x;        // one warp = one chain
    const int b    = blockIdx.x;
    const int c0   = 2 * lane;           // my two columns: c0, c0+1
    const size_t SSTR = (size_t)NB * NT;

    // ---------------- numerator: gold-path score ----------------
    float sc = 0.f;
    int msum = 0;
    {
#pragma unroll
        for (int k = 0; k < 16; k++) {
            int s = 1 + lane + (k << 5);
            if (s < NS) {
                int tp = tags[(s - 1) * NB + b];
                int tc = tags[s * NB + b];
                int mv = mask[s * NB + b];
                float term = trans[tp * NT + tc] + em[((size_t)s * NB + b) * NT + tc];
                sc += term * (float)mv;
                msum += mv;
            }
        }
#pragma unroll
        for (int off = 16; off; off >>= 1) {
            sc   += __shfl_xor_sync(0xffffffffu, sc, off);
            msum += __shfl_xor_sync(0xffffffffu, msum, off);
        }
        int t0 = tags[b];
        sc += start_t[t0] + em[(size_t)b * NT + t0];
        int seq_end = mask[b] + msum - 1;
        int lt = tags[(size_t)seq_end * NB + b];
        sc += end_t[lt];
    }

    // ---------------- mask bitset: lane l holds bits for steps 16l..16l+15 ----------
    unsigned mbits = 0;
#pragma unroll
    for (int k = 0; k < 16; k++) {
        int s = 16 * lane + k;
        mbits |= (unsigned)(mask[s * NB + b] & 1) << k;
    }

    // ---------------- start cp.async em pipeline: slots for steps 1..8 ----------------
    const float* emb2l = em + (size_t)b * NT + c0;   // lane's own 8B per step
#pragma unroll
    for (int t = 1; t <= 8; t++) {
        cp_async8(&emring[t & 7][c0], emb2l + (size_t)t * SSTR);
        CP_COMMIT();
    }

    // ---------------- E row-pair packed: EC<j>[i] = {E[2i][c0+j], E[2i+1][c0+j]} ------
    u64 EC0[32], EC1[32];
#pragma unroll
    for (int i = 0; i < 32; i++) {
        float2 ta = *reinterpret_cast<const float2*>(trans + (2 * i) * NT + c0);
        float2 tb = *reinterpret_cast<const float2*>(trans + (2 * i + 1) * NT + c0);
        EC0[i] = pack2(__expf(ta.x), __expf(tb.x));
        EC1[i] = pack2(__expf(ta.y), __expf(tb.y));
    }

    // ---------------- init recursion state ----------------
    u64 y01;
    {
        float2 e0 = *reinterpret_cast<const float2*>(emb2l);
        float2 s2 = *reinterpret_cast<const float2*>(start_t + c0);
        y01 = pack2(__expf(s2.x + e0.x), __expf(s2.y + e0.y));
        sts64(&qsm[1][lane], y01);
    }
    float Mtot = 0.f;                            // renorm log accumulator (uniform)

    u64 eem01;                                   // exp(em[s]) * 2^-6 for current step
    {
        CP_WAIT(7);
        float2 e1 = *reinterpret_cast<const float2*>(&emring[1][c0]);
        eem01 = pack2(expm6(e1.x), expm6(e1.y));
    }
    __syncwarp();

// One forward step. P = parity (compile-time), RN = fused renormalization.
#define CRF_STEP(S, P, RN)                                                         \
    {                                                                              \
        const ulonglong2* q2 = reinterpret_cast<const ulonglong2*>(qsm[P]);        \
        u64 a0 = 0, a1 = 0, a2 = 0, a3 = 0;                                        \
        u64 a4 = 0, a5 = 0, a6 = 0, a7 = 0;                                        \
        _Pragma("unroll")                                                          \
        for (int m = 0; m < 8; m++) {                                              \
            ulonglong2 qA = q2[2 * m];                                             \
            ulonglong2 qB = q2[2 * m + 1];                                         \
            fma2(a0, qA.x, EC0[4 * m]);     fma2(a1, qA.x, EC1[4 * m]);            \
            fma2(a2, qA.y, EC0[4 * m + 1]); fma2(a3, qA.y, EC1[4 * m + 1]);        \
            fma2(a4, qB.x, EC0[4 * m + 2]); fma2(a5, qB.x, EC1[4 * m + 2]);        \
            fma2(a6, qB.y, EC0[4 * m + 3]); fma2(a7, qB.y, EC1[4 * m + 3]);        \
        }                                                                          \
        u64 A0 = add2(add2(a0, a2), add2(a4, a6));   /* col c0, row-pair packed */ \
        u64 A1 = add2(add2(a1, a3), add2(a5, a7));   /* col c0+1 */                \
        float lo0, hi0, lo1, hi1;                                                  \
        unpack2(A0, lo0, hi0);                                                     \
        unpack2(A1, lo1, hi1);                                                     \
        int mk = (int)((mword >> ((S) & 15)) & 1u);                                \
        u64 cnew = mul2(pack2(lo0 + hi0, lo1 + hi1), eem01);                       \
        if (mk) y01 = cnew;                                                        \
        if (RN) {                                                                  \
            float f0, fx; unpack2(y01, f0, fx);                                    \
            float f = __shfl_sync(0xffffffffu, f0, 0);                             \
            float rf = frcp(f);                                                    \
            y01 = mul2(y01, pack2(rf, rf));                                        \
            Mtot += __logf(f);                                                     \
        }                                                                          \
        sts64(&qsm[(P) ^ 1][lane], y01);                                           \
        __syncwarp();                                                              \
        CP_WAIT(6);                                                                \
        float2 en = *reinterpret_cast<const float2*>(&emring[((S) + 1) & 7][c0]);  \
        eem01 = pack2(expm6(en.x), expm6(en.y));                                   \
        int t = ((S) + 8 < NS) ? ((S) + 8) : (NS - 1);                             \
        cp_async8(&emring[((S) + 8) & 7][c0], emb2l + (size_t)t * SSTR);           \
        CP_COMMIT();                                                               \
    }

    // prologue: steps 1..7, renorm at step 7
    unsigned mword = __shfl_sync(0xffffffffu, mbits, 0);
    CRF_STEP(1, 1, false)
    CRF_STEP(2, 0, false)
    CRF_STEP(3, 1, false)
    CRF_STEP(4, 0, false)
    CRF_STEP(5, 1, false)
    CRF_STEP(6, 0, false)
    CRF_STEP(7, 1, true)

    // main: 63 blocks of 8 steps, renorm fused into last step of each block
    for (int o = 1; o < 64; o++) {
        const int s0 = o << 3;
        mword = __shfl_sync(0xffffffffu, mbits, o >> 1);
        CRF_STEP(s0,     0, false)
        CRF_STEP(s0 + 1, 1, false)
        CRF_STEP(s0 + 2, 0, false)
        CRF_STEP(s0 + 3, 1, false)
        CRF_STEP(s0 + 4, 0, false)
        CRF_STEP(s0 + 5, 1, false)
        CRF_STEP(s0 + 6, 0, false)
        CRF_STEP(s0 + 7, 1, true)
    }
#undef CRF_STEP

    // ---------------- normalizer = Mtot + msum*log(64) + log(sum_j y_j e^{end_j}) ------
    {
        float2 e2 = *reinterpret_cast<const float2*>(end_t + c0);
        float y0, y1; unpack2(y01, y0, y1);
        float v = y0 * __expf(e2.x) + y1 * __expf(e2.y);
#pragma unroll
        for (int off = 16; off; off >>= 1)
            v += __shfl_xor_sync(0xffffffffu, v, off);
        if (lane == 0) {
            const float LOG64 = 4.1588830833596715f;
            g_partial[b] = sc - (Mtot + (float)msum * LOG64 + __logf(v));
            __threadfence();
        }
    }

    // ---------------- merged deterministic final reduction (last block) ----------------
    __syncwarp();
    int last = 0;
    if (lane == 0) {
        unsigned int old = atomicAdd(&g_ctr, 1);
        last = (old == (unsigned int)(gridDim.x - 1));
    }
    last = __shfl_sync(0xffffffffu, last, 0);
    if (last) {
        __threadfence();
        float s = 0.f;
#pragma unroll
        for (int i = 0; i < NB / 32; i++)
            s += g_partial[lane + i * 32];
#pragma unroll
        for (int off = 16; off; off >>= 1)
            s += __shfl_xor_sync(0xffffffffu, s, off);
        if (lane == 0) { out[0] = s; g_ctr = 0; }
    }
}

extern "C" void kernel_launch(void* const* d_in, const int* in_sizes, int n_in,
                              void* d_out, int out_size) {
    const float* em    = (const float*)d_in[0];
    const float* trans = (const float*)d_in[1];
    const float* st    = (const float*)d_in[2];
    const float* et    = (const float*)d_in[3];
    const int*   tags  = (const int*)d_in[4];
    const int*   mask  = (const int*)d_in[5];

    crf_kernel<<<NB, 32>>>(em, trans, st, et, tags, mask, (float*)d_out);
}